// round 1
// baseline (speedup 1.0000x reference)
#include <cuda_runtime.h>
#include <math.h>

#define NCOLS     16384
#define NTHREADS  512
#define VEC4PT    (NCOLS / 4 / NTHREADS)   // 8 float4 per thread
#define CHUNK     (NCOLS / NTHREADS)       // 32 contiguous elems per thread (compaction)
#define KSEL      256
#define CAND_CAP  3072
#define NWARPS    (NTHREADS / 32)

__global__ __launch_bounds__(NTHREADS, 1)
void entmax_topk_kernel(const float* __restrict__ logits,
                        float* __restrict__ out_w,
                        float* __restrict__ out_cnt)
{
    extern __shared__ float sm[];
    float* zs   = sm;            // NCOLS floats: z = logits * 0.5
    float* cand = sm + NCOLS;    // CAND_CAP floats: candidates z > zmax-1

    __shared__ float s_wred[NWARPS];
    __shared__ int   s_warpsum[NWARPS];
    __shared__ int   s_ired[NWARPS];
    __shared__ float s_zmax, s_tau, s_th, s_inv;
    __shared__ int   s_useGe, s_candN;

    const int tid  = threadIdx.x;
    const int lane = tid & 31;
    const int wid  = tid >> 5;
    const int row  = blockIdx.x;

    const float4* src = reinterpret_cast<const float4*>(logits) + (size_t)row * (NCOLS / 4);
    float4*       dst = reinterpret_cast<float4*>(out_w)        + (size_t)row * (NCOLS / 4);

    // ---------- Pass 1: load row, z = 0.5*logit, store to smem, track max ----------
    float lmax = -INFINITY;
    #pragma unroll
    for (int j = 0; j < VEC4PT; ++j) {
        int i = tid + j * NTHREADS;
        float4 v = src[i];
        v.x *= 0.5f; v.y *= 0.5f; v.z *= 0.5f; v.w *= 0.5f;
        reinterpret_cast<float4*>(zs)[i] = v;
        lmax = fmaxf(lmax, fmaxf(fmaxf(v.x, v.y), fmaxf(v.z, v.w)));
    }
    #pragma unroll
    for (int o = 16; o; o >>= 1) lmax = fmaxf(lmax, __shfl_xor_sync(0xffffffffu, lmax, o));
    if (lane == 0) s_wred[wid] = lmax;
    __syncthreads();
    if (wid == 0) {
        float m = (lane < NWARPS) ? s_wred[lane] : -INFINITY;
        #pragma unroll
        for (int o = 16; o; o >>= 1) m = fmaxf(m, __shfl_xor_sync(0xffffffffu, m, o));
        if (lane == 0) s_zmax = m;
    }
    __syncthreads();
    const float zmax   = s_zmax;
    const float cutoff = zmax - 1.0f;   // rigorous lower bound on tau

    // ---------- Pass 2: deterministic compaction of candidates (z > cutoff) ----------
    // Thread t owns contiguous chunk [t*CHUNK, (t+1)*CHUNK). Order-preserving via scan.
    const int base = tid * CHUNK;
    int lc = 0;
    for (int k = 0; k < CHUNK; ++k) lc += (zs[base + k] > cutoff) ? 1 : 0;
    int inc = lc;
    #pragma unroll
    for (int o = 1; o < 32; o <<= 1) {
        int v = __shfl_up_sync(0xffffffffu, inc, o);
        if (lane >= o) inc += v;
    }
    if (lane == 31) s_warpsum[wid] = inc;
    __syncthreads();
    if (wid == 0) {
        int v = (lane < NWARPS) ? s_warpsum[lane] : 0;
        int winc = v;
        #pragma unroll
        for (int o = 1; o < NWARPS; o <<= 1) {
            int u = __shfl_up_sync(0xffffffffu, winc, o);
            if (lane >= o) winc += u;
        }
        if (lane < NWARPS) s_warpsum[lane] = winc - v;   // exclusive warp bases
        if (lane == NWARPS - 1) s_candN = winc;          // total candidates
    }
    __syncthreads();
    const int total  = s_candN;
    if (total <= CAND_CAP) {
        int o = s_warpsum[wid] + (inc - lc);
        for (int k = 0; k < CHUNK; ++k) {
            float z = zs[base + k];
            if (z > cutoff) cand[o++] = z;
        }
    }
    __syncthreads();

    const float* cbuf = (total <= CAND_CAP) ? cand  : zs;
    const int    cn   = (total <= CAND_CAP) ? total : NCOLS;

    // ---------- Warp 0: solve tau (Newton from the left; convex g => monotone) ----------
    if (wid == 0) {
        float tau = cutoff;
        for (int it = 0; it < 24; ++it) {
            float g = 0.f, gp = 0.f;
            for (int i = lane; i < cn; i += 32) {
                float d = cbuf[i] - tau;
                if (d > 0.f) { g = fmaf(d, d, g); gp += d; }
            }
            #pragma unroll
            for (int o = 16; o; o >>= 1) {
                g  += __shfl_xor_sync(0xffffffffu, g,  o);
                gp += __shfl_xor_sync(0xffffffffu, gp, o);
            }
            g -= 1.0f;                       // g(tau) = sum max(z-tau,0)^2 - 1
            if (gp > 0.f) tau += g / (2.0f * gp);
        }

        // support size
        int S = 0;
        for (int i = lane; i < cn; i += 32) S += (cbuf[i] > tau) ? 1 : 0;
        #pragma unroll
        for (int o = 16; o; o >>= 1) S += __shfl_xor_sync(0xffffffffu, S, o);

        // top-K threshold only if support exceeds K (rare): bisect for K-th largest z
        float th = tau;
        int useGe = 0;
        if (S > KSEL) {
            float lo = tau, hi = zmax;
            for (int it = 0; it < 48; ++it) {
                float mid = 0.5f * (lo + hi);
                int c = 0;
                for (int i = lane; i < cn; i += 32) c += (cbuf[i] >= mid) ? 1 : 0;
                #pragma unroll
                for (int o = 16; o; o >>= 1) c += __shfl_xor_sync(0xffffffffu, c, o);
                if (c >= KSEL) lo = mid; else hi = mid;
            }
            th = lo;
            useGe = 1;
        }

        // sum of kept (masked) weights
        float ssum = 0.f;
        for (int i = lane; i < cn; i += 32) {
            float z = cbuf[i];
            bool keep = useGe ? (z >= th) : (z > th);
            if (keep) {
                float d = z - tau;
                if (d > 0.f) ssum = fmaf(d, d, ssum);
            }
        }
        #pragma unroll
        for (int o = 16; o; o >>= 1) ssum += __shfl_xor_sync(0xffffffffu, ssum, o);

        if (lane == 0) {
            s_tau = tau;
            s_th  = th;
            s_useGe = useGe;
            s_inv = 1.0f / (ssum + 1e-8f);
        }
    }
    __syncthreads();

    const float tau = s_tau, th = s_th, inv = s_inv;
    const int useGe = s_useGe;

    // ---------- Pass 3: write weights, count selected (> 1e-6) ----------
    int sel = 0;
    #pragma unroll
    for (int j = 0; j < VEC4PT; ++j) {
        int i = tid + j * NTHREADS;
        float4 v = reinterpret_cast<float4*>(zs)[i];
        float4 w;
        {
            float d = v.x - tau; bool k = useGe ? (v.x >= th) : (v.x > th);
            w.x = (k && d > 0.f) ? d * d * inv : 0.f; sel += (w.x > 1e-6f);
        }
        {
            float d = v.y - tau; bool k = useGe ? (v.y >= th) : (v.y > th);
            w.y = (k && d > 0.f) ? d * d * inv : 0.f; sel += (w.y > 1e-6f);
        }
        {
            float d = v.z - tau; bool k = useGe ? (v.z >= th) : (v.z > th);
            w.z = (k && d > 0.f) ? d * d * inv : 0.f; sel += (w.z > 1e-6f);
        }
        {
            float d = v.w - tau; bool k = useGe ? (v.w >= th) : (v.w > th);
            w.w = (k && d > 0.f) ? d * d * inv : 0.f; sel += (w.w > 1e-6f);
        }
        dst[i] = w;
    }
    #pragma unroll
    for (int o = 16; o; o >>= 1) sel += __shfl_xor_sync(0xffffffffu, sel, o);
    if (lane == 0) s_ired[wid] = sel;
    __syncthreads();
    if (tid == 0) {
        int t = 0;
        #pragma unroll
        for (int w = 0; w < NWARPS; ++w) t += s_ired[w];
        out_cnt[row] = (float)t;
    }
}

extern "C" void kernel_launch(void* const* d_in, const int* in_sizes, int n_in,
                              void* d_out, int out_size)
{
    const float* logits = (const float*)d_in[0];
    float* out = (float*)d_out;
    const int B = in_sizes[0] / NCOLS;

    const size_t smem = (size_t)(NCOLS + CAND_CAP) * sizeof(float);  // 77824 B
    cudaFuncSetAttribute(entmax_topk_kernel,
                         cudaFuncAttributeMaxDynamicSharedMemorySize, (int)smem);
    entmax_topk_kernel<<<B, NTHREADS, smem>>>(logits, out, out + (size_t)B * NCOLS);
}

// round 2
// speedup vs baseline: 3.1173x; 3.1173x over previous
#include <cuda_runtime.h>
#include <math.h>

#define NCOLS  16384
#define NT     512
#define V4     (NCOLS / 4 / NT)     // 8 float4 per thread
#define KSEL   256
#define CAP    6144
#define NW     (NT / 32)
#define RST    8                    // register stash capacity per thread
#define REGCN  512                  // register-cache tau path when cn <= 512

__global__ __launch_bounds__(NT, 3)
void entmax_topk_kernel(const float* __restrict__ logits,
                        float* __restrict__ out_w,
                        float* __restrict__ out_cnt)
{
    __shared__ float cand[CAP];
    __shared__ float s_f[NW];
    __shared__ int   s_i[NW];
    __shared__ float s_tau, s_th, s_inv;
    __shared__ int   s_useGe, s_cn;

    const int tid  = threadIdx.x;
    const int lane = tid & 31;
    const int wid  = tid >> 5;
    const int row  = blockIdx.x;

    const float4* src = reinterpret_cast<const float4*>(logits) + (size_t)row * (NCOLS / 4);
    float4*       dst = reinterpret_cast<float4*>(out_w)        + (size_t)row * (NCOLS / 4);

    // ---------- Pass A: row max (raw logits; z = 0.5*x) ----------
    float lmax = -INFINITY;
    #pragma unroll
    for (int j = 0; j < V4; ++j) {
        float4 v = src[tid + j * NT];
        lmax = fmaxf(lmax, fmaxf(fmaxf(v.x, v.y), fmaxf(v.z, v.w)));
    }
    #pragma unroll
    for (int o = 16; o; o >>= 1) lmax = fmaxf(lmax, __shfl_xor_sync(0xffffffffu, lmax, o));
    if (lane == 0) s_f[wid] = lmax;
    __syncthreads();
    if (wid == 0) {
        float m = (lane < NW) ? s_f[lane] : -INFINITY;
        #pragma unroll
        for (int o = 16; o; o >>= 1) m = fmaxf(m, __shfl_xor_sync(0xffffffffu, m, o));
        if (lane == 0) s_f[0] = m;
    }
    __syncthreads();
    const float zmax   = 0.5f * s_f[0];
    const float cutoff = zmax - 1.0f;        // rigorous lower bound on tau
    __syncthreads();                          // s_f reuse guard

    // ---------- Pass B: re-read (L2), compact candidates z > cutoff ----------
    float stash[RST];
    int lc = 0;
    #pragma unroll
    for (int j = 0; j < V4; ++j) {
        float4 v = src[tid + j * NT];
        float z;
        z = 0.5f * v.x; if (z > cutoff) { if (lc < RST) stash[lc] = z; ++lc; }
        z = 0.5f * v.y; if (z > cutoff) { if (lc < RST) stash[lc] = z; ++lc; }
        z = 0.5f * v.z; if (z > cutoff) { if (lc < RST) stash[lc] = z; ++lc; }
        z = 0.5f * v.w; if (z > cutoff) { if (lc < RST) stash[lc] = z; ++lc; }
    }
    // deterministic exclusive scan of per-thread counts
    int inc = lc;
    #pragma unroll
    for (int o = 1; o < 32; o <<= 1) {
        int t = __shfl_up_sync(0xffffffffu, inc, o);
        if (lane >= o) inc += t;
    }
    if (lane == 31) s_i[wid] = inc;
    __syncthreads();
    if (wid == 0) {
        int v = (lane < NW) ? s_i[lane] : 0;
        int winc = v;
        #pragma unroll
        for (int o = 1; o < NW; o <<= 1) {
            int u = __shfl_up_sync(0xffffffffu, winc, o);
            if (lane >= o) winc += u;
        }
        if (lane < NW) s_i[lane] = winc - v;       // exclusive warp bases
        if (lane == NW - 1) s_cn = winc;
    }
    __syncthreads();
    const int  cn      = s_cn;
    const bool useSmem = (cn <= CAP);
    if (useSmem && lc > 0) {
        int o = s_i[wid] + (inc - lc);
        if (lc <= RST) {
            for (int k = 0; k < lc; ++k) cand[o + k] = stash[k];
        } else {  // stash overflow (adversarial only): re-read from L2
            int w = 0;
            #pragma unroll
            for (int j = 0; j < V4; ++j) {
                float4 v = src[tid + j * NT];
                float z;
                z = 0.5f * v.x; if (z > cutoff) cand[o + w++] = z;
                z = 0.5f * v.y; if (z > cutoff) cand[o + w++] = z;
                z = 0.5f * v.z; if (z > cutoff) cand[o + w++] = z;
                z = 0.5f * v.w; if (z > cutoff) cand[o + w++] = z;
            }
        }
    }
    __syncthreads();

    // ---------- Warp 0: solve tau; support; optional top-K; norm ----------
    if (wid == 0) {
        float tau = cutoff, th, inv;
        int useGe = 0;

        if (useSmem && cn <= REGCN) {
            // register-cached fast path: zero LDS inside iterations
            float rv[REGCN / 32];
            #pragma unroll
            for (int r = 0; r < REGCN / 32; ++r) {
                int idx = r * 32 + lane;
                rv[r] = (idx < cn) ? cand[idx] : -1e30f;
            }
            float gfin = 0.f;
            for (int it = 0; it < 24; ++it) {
                float g = 0.f, gp = 0.f;
                #pragma unroll
                for (int r = 0; r < REGCN / 32; ++r) {
                    float d = rv[r] - tau;
                    if (d > 0.f) { g = fmaf(d, d, g); gp += d; }
                }
                #pragma unroll
                for (int o = 16; o; o >>= 1) {
                    g  += __shfl_xor_sync(0xffffffffu, g,  o);
                    gp += __shfl_xor_sync(0xffffffffu, gp, o);
                }
                gfin = g;
                g -= 1.0f;
                if (gp <= 0.f) break;
                float step = g / (2.0f * gp);
                tau += step;
                if (step < 1e-7f) break;
            }
            int S = 0;
            #pragma unroll
            for (int r = 0; r < REGCN / 32; ++r) S += (rv[r] > tau) ? 1 : 0;
            #pragma unroll
            for (int o = 16; o; o >>= 1) S += __shfl_xor_sync(0xffffffffu, S, o);

            th = tau;
            float ssum = gfin;   // sum of (z-tau)_+^2 at final tau
            if (S > KSEL) {      // rare: bisect K-th largest z among candidates
                useGe = 1;
                float lo = tau, hi = zmax;
                for (int it = 0; it < 48; ++it) {
                    float mid = 0.5f * (lo + hi);
                    int c = 0;
                    #pragma unroll
                    for (int r = 0; r < REGCN / 32; ++r) c += (rv[r] >= mid) ? 1 : 0;
                    #pragma unroll
                    for (int o = 16; o; o >>= 1) c += __shfl_xor_sync(0xffffffffu, c, o);
                    if (c >= KSEL) lo = mid; else hi = mid;
                }
                th = lo;
                ssum = 0.f;
                #pragma unroll
                for (int r = 0; r < REGCN / 32; ++r) {
                    float z = rv[r];
                    float d = z - tau;
                    if (z >= th && d > 0.f) ssum = fmaf(d, d, ssum);
                }
                #pragma unroll
                for (int o = 16; o; o >>= 1) ssum += __shfl_xor_sync(0xffffffffu, ssum, o);
            }
            inv = 1.0f / (ssum + 1e-8f);
        } else {
            // generic path: smem candidates, or full row from global (huge-support fallback)
            const float* cb = useSmem ? cand : (logits + (size_t)row * NCOLS);
            const float  sc = useSmem ? 1.0f : 0.5f;
            const int    n  = useSmem ? cn : NCOLS;

            float gfin = 0.f;
            for (int it = 0; it < 24; ++it) {
                float g = 0.f, gp = 0.f;
                for (int i = lane; i < n; i += 32) {
                    float d = sc * cb[i] - tau;
                    if (d > 0.f) { g = fmaf(d, d, g); gp += d; }
                }
                #pragma unroll
                for (int o = 16; o; o >>= 1) {
                    g  += __shfl_xor_sync(0xffffffffu, g,  o);
                    gp += __shfl_xor_sync(0xffffffffu, gp, o);
                }
                gfin = g;
                g -= 1.0f;
                if (gp <= 0.f) break;
                float step = g / (2.0f * gp);
                tau += step;
                if (step < 1e-7f) break;
            }
            int S = 0;
            for (int i = lane; i < n; i += 32) S += (sc * cb[i] > tau) ? 1 : 0;
            #pragma unroll
            for (int o = 16; o; o >>= 1) S += __shfl_xor_sync(0xffffffffu, S, o);

            th = tau;
            float ssum = gfin;
            if (S > KSEL) {
                useGe = 1;
                float lo = tau, hi = zmax;
                for (int it = 0; it < 48; ++it) {
                    float mid = 0.5f * (lo + hi);
                    int c = 0;
                    for (int i = lane; i < n; i += 32) c += (sc * cb[i] >= mid) ? 1 : 0;
                    #pragma unroll
                    for (int o = 16; o; o >>= 1) c += __shfl_xor_sync(0xffffffffu, c, o);
                    if (c >= KSEL) lo = mid; else hi = mid;
                }
                th = lo;
                ssum = 0.f;
                for (int i = lane; i < n; i += 32) {
                    float z = sc * cb[i];
                    float d = z - tau;
                    if (z >= th && d > 0.f) ssum = fmaf(d, d, ssum);
                }
                #pragma unroll
                for (int o = 16; o; o >>= 1) ssum += __shfl_xor_sync(0xffffffffu, ssum, o);
            }
            inv = 1.0f / (ssum + 1e-8f);
        }

        if (lane == 0) {
            s_tau = tau; s_th = th; s_useGe = useGe; s_inv = inv;
        }
    }
    __syncthreads();

    const float tau = s_tau, th = s_th, inv = s_inv;
    const int   useGe = s_useGe;

    // ---------- Pass C: re-read (L2), write weights, count > 1e-6 ----------
    int sel = 0;
    #pragma unroll
    for (int j = 0; j < V4; ++j) {
        float4 v = src[tid + j * NT];
        float4 w;
        {
            float z = 0.5f * v.x, d = z - tau;
            bool keep = useGe ? (z >= th && d > 0.f) : (d > 0.f);
            w.x = keep ? d * d * inv : 0.f; sel += (w.x > 1e-6f);
        }
        {
            float z = 0.5f * v.y, d = z - tau;
            bool keep = useGe ? (z >= th && d > 0.f) : (d > 0.f);
            w.y = keep ? d * d * inv : 0.f; sel += (w.y > 1e-6f);
        }
        {
            float z = 0.5f * v.z, d = z - tau;
            bool keep = useGe ? (z >= th && d > 0.f) : (d > 0.f);
            w.z = keep ? d * d * inv : 0.f; sel += (w.z > 1e-6f);
        }
        {
            float z = 0.5f * v.w, d = z - tau;
            bool keep = useGe ? (z >= th && d > 0.f) : (d > 0.f);
            w.w = keep ? d * d * inv : 0.f; sel += (w.w > 1e-6f);
        }
        dst[tid + j * NT] = w;
    }
    #pragma unroll
    for (int o = 16; o; o >>= 1) sel += __shfl_xor_sync(0xffffffffu, sel, o);
    if (lane == 0) s_i[wid] = sel;
    __syncthreads();
    if (tid == 0) {
        int t = 0;
        #pragma unroll
        for (int w = 0; w < NW; ++w) t += s_i[w];
        out_cnt[row] = (float)t;
    }
}

extern "C" void kernel_launch(void* const* d_in, const int* in_sizes, int n_in,
                              void* d_out, int out_size)
{
    const float* logits = (const float*)d_in[0];
    float* out = (float*)d_out;
    const int B = in_sizes[0] / NCOLS;
    entmax_topk_kernel<<<B, NT>>>(logits, out, out + (size_t)B * NCOLS);
}